// round 15
// baseline (speedup 1.0000x reference)
#include <cuda_runtime.h>
#include <cuda_bf16.h>
#include <math_constants.h>

#define CC      128
#define BATCH   64
#define HW      3136
#define NCH     8
#define CHUNK_B (BATCH / NCH)            // 8
#define CHUNK_SZ (CHUNK_B * HW)          // 25088
#define NTOT    ((size_t)BATCH * HW)     // 200704
#define HW4     (HW / 4)                 // 784
#define NPLANES (BATCH * CC)             // 8192

// Scratch
__device__ float g_pmax[NPLANES];        // raw per-plane max
__device__ float g_pmin[NPLANES];        // raw per-plane min
__device__ float g_psum[NPLANES];        // per-plane sum of bf16-quantized x
__device__ float g_avg[CC];
__device__ float g_scale[CC];
__device__ unsigned int g_ctr = 0;

__device__ __forceinline__ float qbf(float v) {
    return __bfloat162float(__float2bfloat16(v));
}

// Quantize a pair to bf16 (one CVT), expand back via bit ops.
__device__ __forceinline__ float2 q2(float a, float b) {
    __nv_bfloat162 p = __float22bfloat162_rn(make_float2(a, b));
    unsigned int u = *reinterpret_cast<unsigned int*>(&p);
    return make_float2(__uint_as_float(u << 16), __uint_as_float(u & 0xffff0000u));
}

// ---------------------------------------------------------------------------
// Kernel 1: per-plane max/min/sum. grid = 8192 (one 12.25KB plane per block),
// 128 threads, PLAIN LDG.128 linear reads (R7's slow v8 path is gone; this is
// the balanced-grid shape R4's 1024-block version lacked).
// Last-finishing block does the per-channel combine (exact _q chain).
// ---------------------------------------------------------------------------
__global__ __launch_bounds__(128) void rbn_reduce(const float* __restrict__ x) {
    const int p   = blockIdx.x;
    const int tid = threadIdx.x;
    const float4* px = reinterpret_cast<const float4*>(x) + (size_t)p * HW4;

    // 784 = 6*128 + 16 : six front-batched loads + 16-thread tail.
    float4 v[6];
    #pragma unroll
    for (int j = 0; j < 6; ++j) v[j] = __ldg(px + tid + j * 128);
    const bool tail = (tid < 16);
    float4 vt;
    if (tail) vt = __ldg(px + tid + 768);

    float vmax = -CUDART_INF_F, vmin = CUDART_INF_F, vsum = 0.0f;
    #pragma unroll
    for (int j = 0; j < 6; ++j) {
        vmax = fmaxf(vmax, fmaxf(fmaxf(v[j].x, v[j].y), fmaxf(v[j].z, v[j].w)));
        vmin = fminf(vmin, fminf(fminf(v[j].x, v[j].y), fminf(v[j].z, v[j].w)));
        float2 p0 = q2(v[j].x, v[j].y);
        float2 p1 = q2(v[j].z, v[j].w);
        vsum += (p0.x + p0.y) + (p1.x + p1.y);
    }
    if (tail) {
        vmax = fmaxf(vmax, fmaxf(fmaxf(vt.x, vt.y), fmaxf(vt.z, vt.w)));
        vmin = fminf(vmin, fminf(fminf(vt.x, vt.y), fminf(vt.z, vt.w)));
        float2 p0 = q2(vt.x, vt.y);
        float2 p1 = q2(vt.z, vt.w);
        vsum += (p0.x + p0.y) + (p1.x + p1.y);
    }

    // block reduce: 4 warps
    __shared__ float smax[4], smin[4], ssum[4];
    __shared__ int s_last;
    const int lane = tid & 31, wid = tid >> 5;
    #pragma unroll
    for (int off = 16; off > 0; off >>= 1) {
        vmax = fmaxf(vmax, __shfl_xor_sync(0xffffffff, vmax, off));
        vmin = fminf(vmin, __shfl_xor_sync(0xffffffff, vmin, off));
        vsum += __shfl_xor_sync(0xffffffff, vsum, off);
    }
    if (lane == 0) { smax[wid] = vmax; smin[wid] = vmin; ssum[wid] = vsum; }
    __syncthreads();
    if (tid == 0) {
        vmax = fmaxf(fmaxf(smax[0], smax[1]), fmaxf(smax[2], smax[3]));
        vmin = fminf(fminf(smin[0], smin[1]), fminf(smin[2], smin[3]));
        vsum = (ssum[0] + ssum[1]) + (ssum[2] + ssum[3]);
        g_pmax[p] = vmax;      // raw (quantize at chunk level; rounding monotone)
        g_pmin[p] = vmin;
        g_psum[p] = vsum;
        __threadfence();
        unsigned int old = atomicAdd(&g_ctr, 1u);
        s_last = (old == (unsigned)(NPLANES - 1));
    }
    __syncthreads();

    if (s_last) {
        // Fused combine: one channel per thread, exact reference _q() chain.
        if (tid < CC) {
            const int c = tid;
            float sum_max = 0.f, sum_min = 0.f, total = 0.f;
            #pragma unroll
            for (int k = 0; k < NCH; ++k) {
                float cmax = -CUDART_INF_F, cmin = CUDART_INF_F, csum = 0.f;
                #pragma unroll
                for (int bb = 0; bb < CHUNK_B; ++bb) {
                    const int pp = (k * CHUNK_B + bb) * CC + c;
                    cmax = fmaxf(cmax, g_pmax[pp]);
                    cmin = fminf(cmin, g_pmin[pp]);
                    csum += g_psum[pp];
                }
                sum_max += qbf(cmax);   // chunk max of q(x) == q(chunk max of x)
                sum_min += qbf(cmin);
                total   += csum;
            }
            sum_max = qbf(sum_max);
            sum_min = qbf(sum_min);
            float avg_max = qbf(sum_max / (float)NCH);
            float avg_min = qbf(sum_min / (float)NCH);
            total = qbf(total);
            float avg = qbf(total / (float)NTOT);
            const float scale_fix = (float)(1.0 / sqrt(2.0 * log((double)CHUNK_SZ)));
            float scale = qbf(1.0f / ((avg_max - avg_min) * scale_fix + 1e-5f));
            g_avg[c]   = avg;
            g_scale[c] = scale;
        }
        __syncthreads();
        if (tid == 0) g_ctr = 0;   // reset for next graph replay
    }
}

// ---------------------------------------------------------------------------
// Kernel 2: apply. out = q(q((q(x)-avg)*scale)*q(gamma)+beta)
// One plane per block, grid 8192 x 256, but planes processed in REVERSE
// order: reduce finished reading planes 0->8191, so L2 retains the highest
// planes -> apply's first waves read those while still resident. Apply in
// turn finishes on low planes, which the NEXT replay's reduce reads first.
// Reads __ldg; writes __stcs (evict-first, protects resident x).
// ---------------------------------------------------------------------------
__global__ __launch_bounds__(256) void rbn_apply(const float* __restrict__ x,
                                                 const float* __restrict__ gamma,
                                                 const float* __restrict__ beta,
                                                 float* __restrict__ out) {
    const int tid = threadIdx.x;
    const int plane = (NPLANES - 1) - blockIdx.x;   // reverse scheduling order
    const int c = plane & (CC - 1);
    const size_t plane4 = (size_t)plane * HW4;
    const float4* px = reinterpret_cast<const float4*>(x) + plane4;
    float4* po = reinterpret_cast<float4*>(out) + plane4;

    const float avg   = g_avg[c];
    const float scale = g_scale[c];
    const float g     = qbf(__ldg(gamma + c));
    const float bt    = __ldg(beta + c);   // beta NOT quantized in reference

    // 784 = 3*256 + 16 : three front-batched loads + 16-thread tail.
    float4 v[3];
    #pragma unroll
    for (int j = 0; j < 3; ++j) v[j] = __ldg(px + tid + j * 256);
    const bool tail = (tid < 16);
    float4 vt;
    if (tail) vt = __ldg(px + tid + 768);

    #pragma unroll
    for (int j = 0; j < 3; ++j) {
        float2 qa = q2(v[j].x, v[j].y);
        float2 qb = q2(v[j].z, v[j].w);
        float2 ta = q2((qa.x - avg) * scale, (qa.y - avg) * scale);
        float2 tb = q2((qb.x - avg) * scale, (qb.y - avg) * scale);
        float2 oa = q2(ta.x * g + bt, ta.y * g + bt);
        float2 ob = q2(tb.x * g + bt, tb.y * g + bt);
        __stcs(po + tid + j * 256, make_float4(oa.x, oa.y, ob.x, ob.y));
    }
    if (tail) {
        float2 qa = q2(vt.x, vt.y);
        float2 qb = q2(vt.z, vt.w);
        float2 ta = q2((qa.x - avg) * scale, (qa.y - avg) * scale);
        float2 tb = q2((qb.x - avg) * scale, (qb.y - avg) * scale);
        float2 oa = q2(ta.x * g + bt, ta.y * g + bt);
        float2 ob = q2(tb.x * g + bt, tb.y * g + bt);
        __stcs(po + tid + 768, make_float4(oa.x, oa.y, ob.x, ob.y));
    }
}

// ---------------------------------------------------------------------------
extern "C" void kernel_launch(void* const* d_in, const int* in_sizes, int n_in,
                              void* d_out, int out_size) {
    const float* x     = (const float*)d_in[0];
    const float* gamma = (const float*)d_in[1];
    const float* beta  = (const float*)d_in[2];
    float* out = (float*)d_out;

    rbn_reduce<<<NPLANES, 128>>>(x);
    rbn_apply<<<NPLANES, 256>>>(x, gamma, beta, out);
}